// round 16
// baseline (speedup 1.0000x reference)
#include <cuda_runtime.h>
#include <cuda_fp16.h>
#include <math.h>
#include <stdint.h>

#define BB 4
#define TT 2048
#define DD 768
#define NH 12
#define HD 64
#define WIN 64
#define TD3 (3*DD)
#define KK 768             // GEMM K (plain fp16 both operands)
#define KC 32              // k per pipeline chunk
#define NC (KK/KC)         // 24 chunks
#define PS 5               // pipeline stages
#define LDT 40             // padded smem row (fp16 elems) -> 80 bytes
#define TILE_BYTES (128*LDT*2)          // 10240 per operand tile
#define STAGE_BYTES (2*TILE_BYTES)      // 20480
#define GEMM_SMEM (PS*STAGE_BYTES)      // 102400

// attention smem layout (bytes).  Ph ALIASES the union of Qh and Kh.
#define QH_OFF   0                       // Qh fp16 [64][72]   9216B
#define KH_OFF   9216                    // Kh fp16 [192][72] 27648B (ends 36864)
#define PH_OFF   0                       // Ph fp16 [64][200] 25600B (alias Qh+Kh)
#define VHI_OFF  36864                   // Vhi fp16 [192][72] 27648B
#define PMAX_OFF 64512                   // fp32 [4][64] 1024B
#define PSUM_OFF 65536                   // fp32 [4][64] 1024B
#define MS_OFF   66560                   // int [192] 768B
#define ATTN_SMEM_BYTES 67328

// ---------------- scratch (device globals: allocation-free rule) -----------
__device__ __half g_qkvh[(size_t)BB*TT*TD3];         // [B,T,3D] fp16 (pre-rope)
__device__ __half g_ah  [(size_t)BB*TT*KK];          // hidden fp16
__device__ __half g_attnx[(size_t)BB*TT*KK];         // attn out fp16
__device__ __half g_wqkvh[(size_t)TD3*KK];           // Wqkv fp16
__device__ __half g_woh [(size_t)DD*KK];             // Wo fp16
__device__ float  g_tab [(size_t)TT*64];             // rope (cos,sin) pairs [t][j]

typedef unsigned long long u64;

// ---------------- PTX helpers (baseline ISA only) ---------------------------
__device__ __forceinline__ uint32_t smem_u32(const void* p){
    uint32_t a;
    asm("{ .reg .u64 t; cvta.to.shared.u64 t, %1; cvt.u32.u64 %0, t; }"
        : "=r"(a) : "l"(p));
    return a;
}
__device__ __forceinline__ void cp16(uint32_t d, const void* s){
    asm volatile("cp.async.cg.shared.global [%0], [%1], 16;"
                 :: "r"(d), "l"(s) : "memory");
}
__device__ __forceinline__ void cp_commit(){
    asm volatile("cp.async.commit_group;" ::: "memory");
}
template<int N>
__device__ __forceinline__ void cp_wait(){
    asm volatile("cp.async.wait_group %0;" :: "n"(N) : "memory");
}
__device__ __forceinline__ void ldsm_x4(uint32_t &r0,uint32_t &r1,uint32_t &r2,uint32_t &r3,
                                        uint32_t addr){
    asm volatile("ldmatrix.sync.aligned.m8n8.x4.shared.b16 {%0,%1,%2,%3}, [%4];"
                 : "=r"(r0),"=r"(r1),"=r"(r2),"=r"(r3) : "r"(addr));
}
__device__ __forceinline__ void ldsm_x4t(uint32_t &r0,uint32_t &r1,uint32_t &r2,uint32_t &r3,
                                         uint32_t addr){
    asm volatile("ldmatrix.sync.aligned.m8n8.x4.trans.shared.b16 {%0,%1,%2,%3}, [%4];"
                 : "=r"(r0),"=r"(r1),"=r"(r2),"=r"(r3) : "r"(addr));
}
__device__ __forceinline__ void mma16816(float* d, const uint32_t* a, const uint32_t* b){
    asm volatile("mma.sync.aligned.m16n8k16.row.col.f32.f16.f16.f32 "
        "{%0,%1,%2,%3}, {%4,%5,%6,%7}, {%8,%9}, {%0,%1,%2,%3};"
        : "+f"(d[0]),"+f"(d[1]),"+f"(d[2]),"+f"(d[3])
        : "r"(a[0]),"r"(a[1]),"r"(a[2]),"r"(a[3]), "r"(b[0]),"r"(b[1]));
}
__device__ __forceinline__ uint32_t packh2(__half a, __half b){
    return (uint32_t)__half_as_ushort(a) | ((uint32_t)__half_as_ushort(b) << 16);
}

// ---------------------------------------------------------------------------
// fp32 -> fp16 conversion (weights + hidden states) + rope table, one launch.
// ---------------------------------------------------------------------------
__global__ void conv_all(const float* __restrict__ wqkv, const float* __restrict__ wo,
                         const float* __restrict__ hs,
                         __half* __restrict__ wqkvh, __half* __restrict__ woh,
                         __half* __restrict__ ah, float* __restrict__ tab)
{
    const int n1 = TD3*DD/4;
    const int n2 = DD*DD/4;
    const int n3 = BB*TT*DD/4;
    const int n4 = TT*32;                 // rope table entries
    int idx = blockIdx.x * blockDim.x + threadIdx.x;
    if (idx >= n1 + n2 + n3 + n4) return;
    if (idx >= n1 + n2 + n3) {
        int i = idx - n1 - n2 - n3;
        int t = i >> 5, j = i & 31;
        const float c0 = 0.41524101186092029f;   // log2(10000)/32
        float inv = exp2f(-c0 * (float)j);
        float sn, cs;
        sincosf((float)t * inv, &sn, &cs);
        tab[t*64 + 2*j]     = cs;
        tab[t*64 + 2*j + 1] = sn;
        return;
    }
    const float* src; __half* dst; int i;
    if (idx < n1)            { src = wqkv; dst = wqkvh; i = idx; }
    else if (idx < n1 + n2)  { src = wo;   dst = woh;   i = idx - n1; }
    else                     { src = hs;   dst = ah;    i = idx - n1 - n2; }
    float4 v = *(const float4*)(src + (size_t)i*4);
    uint2 o = make_uint2(packh2(__float2half_rn(v.x), __float2half_rn(v.y)),
                         packh2(__float2half_rn(v.z), __float2half_rn(v.w)));
    *(uint2*)(dst + (size_t)i*4) = o;
}

// ---------------------------------------------------------------------------
// HMMA GEMM: C[m,n] = sum_{k<768} A[m,k] * B[n,k]   (fp16 -> fp32 or fp16)
// KC=32, PS=5, cp_wait<3>: 4 stages in flight for deep latency hiding.
// ---------------------------------------------------------------------------
template<bool HOUT>
__global__ void __launch_bounds__(256, 2)
gemm_mma(const __half* __restrict__ A, const __half* __restrict__ B,
         void* __restrict__ Cv, int N)
{
    extern __shared__ __align__(16) char smem[];
    const uint32_t sb = smem_u32(smem);
    const int tid  = threadIdx.x;
    const int lane = tid & 31;
    const int warp = tid >> 5;
    const int bm = blockIdx.y * 128;
    const int bn = blockIdx.x * 128;
    const int wm = warp & 1;
    const int wn = warp >> 1;

    // loader: per stage 1024 cp16 (A 512 + B 512), 4 per thread (2A + 2B).
    const __half* asp[2]; uint32_t adf[2];
    const __half* bsp[2]; uint32_t bdf[2];
#pragma unroll
    for (int h = 0; h < 2; h++) {
        int idx = tid + h * 256;          // 0..511
        int row = idx >> 2, seg = idx & 3;
        asp[h] = A + (size_t)(bm + row) * KK + seg * 8;
        bsp[h] = B + (size_t)(bn + row) * KK + seg * 8;
        adf[h] = (uint32_t)(row * (LDT*2) + seg * 16);
        bdf[h] = adf[h] + TILE_BYTES;
    }

#pragma unroll
    for (int s = 0; s < PS - 1; s++) {
        uint32_t st = sb + s * STAGE_BYTES;
#pragma unroll
        for (int h = 0; h < 2; h++) {
            cp16(st + adf[h], asp[h] + s * KC);
            cp16(st + bdf[h], bsp[h] + s * KC);
        }
        cp_commit();
    }

    float acc[4][4][4];
#pragma unroll
    for (int mi = 0; mi < 4; mi++)
#pragma unroll
        for (int ni = 0; ni < 4; ni++)
#pragma unroll
            for (int r = 0; r < 4; r++) acc[mi][ni][r] = 0.f;

    const uint32_t a_row = (uint32_t)(wm * 64 + (lane & 15));
    const uint32_t a_colb = (uint32_t)((lane >> 4) * 16);
    const uint32_t b_row4 = (uint32_t)(wn * 32 + (lane & 7) + ((lane >> 4) << 3));
    const uint32_t b_colb4 = (uint32_t)(((lane >> 3) & 1) * 16);

    for (int i = 0; i < NC; i++) {
        cp_wait<PS - 2>();
        __syncthreads();

        int nc = i + PS - 1;
        if (nc < NC) {
            uint32_t st = sb + (nc % PS) * STAGE_BYTES;
#pragma unroll
            for (int h = 0; h < 2; h++) {
                cp16(st + adf[h], asp[h] + nc * KC);
                cp16(st + bdf[h], bsp[h] + nc * KC);
            }
        }
        cp_commit();

        uint32_t st = sb + (i % PS) * STAGE_BYTES;
#pragma unroll
        for (int ks = 0; ks < 2; ks++) {
            uint32_t a[4][4], b[4][2];
#pragma unroll
            for (int mi = 0; mi < 4; mi++) {
                uint32_t addr = st + (a_row + mi * 16) * (LDT*2) + ks * 32 + a_colb;
                ldsm_x4(a[mi][0], a[mi][1], a[mi][2], a[mi][3], addr);
            }
#pragma unroll
            for (int p = 0; p < 2; p++) {
                uint32_t addr = st + TILE_BYTES + (b_row4 + p * 16) * (LDT*2)
                              + ks * 32 + b_colb4;
                ldsm_x4(b[2*p][0], b[2*p][1], b[2*p+1][0], b[2*p+1][1], addr);
            }
#pragma unroll
            for (int mi = 0; mi < 4; mi++)
#pragma unroll
                for (int ni = 0; ni < 4; ni++)
                    mma16816(acc[mi][ni], a[mi], b[ni]);
        }
    }

    const int g = lane >> 2, t = lane & 3;
#pragma unroll
    for (int mi = 0; mi < 4; mi++) {
        int m0 = bm + wm * 64 + mi * 16 + g;
#pragma unroll
        for (int ni = 0; ni < 4; ni++) {
            int n0 = bn + wn * 32 + ni * 8 + 2 * t;
            if (HOUT) {
                __half* C = (__half*)Cv;
                *(uint32_t*)&C[(size_t)m0 * N + n0] =
                    packh2(__float2half_rn(acc[mi][ni][0]),
                           __float2half_rn(acc[mi][ni][1]));
                *(uint32_t*)&C[(size_t)(m0 + 8) * N + n0] =
                    packh2(__float2half_rn(acc[mi][ni][2]),
                           __float2half_rn(acc[mi][ni][3]));
            } else {
                float* C = (float*)Cv;
                *(float2*)&C[(size_t)m0 * N + n0] =
                    make_float2(acc[mi][ni][0], acc[mi][ni][1]);
                *(float2*)&C[(size_t)(m0 + 8) * N + n0] =
                    make_float2(acc[mi][ni][2], acc[mi][ni][3]);
            }
        }
    }
}

// ---------------------------------------------------------------------------
// Sliding-window attention, fully on HMMA, 2 CTAs/SM (Ph aliases Qh+Kh):
//   K fragments via ldsm_x4 pairs, V via ldsm_x4t.
// ---------------------------------------------------------------------------
__global__ void __launch_bounds__(256, 2)
attn_kernel(const __half* __restrict__ qkvh, const int* __restrict__ amask,
            const float* __restrict__ tab, __half* __restrict__ attnx)
{
    extern __shared__ __align__(16) char sm[];
    __half* Qh   = (__half*)(sm + QH_OFF);    // [64][72]   (aliased by Ph)
    __half* Kh   = (__half*)(sm + KH_OFF);    // [192][72]  (aliased by Ph)
    __half* Ph   = (__half*)(sm + PH_OFF);    // [64][200]
    __half* Vhi  = (__half*)(sm + VHI_OFF);   // [192][72]
    float*  pmax = (float*)(sm + PMAX_OFF);   // [4][64]
    float*  psum = (float*)(sm + PSUM_OFF);   // [4][64]
    int*    Ms   = (int*)(sm + MS_OFF);       // [192]

    const int tid = threadIdx.x;
    const int qb = blockIdx.x, h = blockIdx.y, b = blockIdx.z;
    const int q0 = qb * 64;
    const int ks = max(0, q0 - WIN);
    const int ke = min(TT, q0 + 64 + WIN);
    const int klen = ke - ks;
    const __half* qbase = qkvh + (size_t)b * TT * TD3;
    const uint32_t vhi_smem = smem_u32(Vhi);

    // ---- V: cp.async copy (zero-fill beyond klen) ----
#pragma unroll
    for (int it = 0; it < 6; it++) {
        int idx = tid + it * 256;
        int kk = idx >> 3, seg = idx & 7;
        if (kk < klen) {
            cp16(vhi_smem + kk * 144 + seg * 16,
                 qbase + (size_t)(ks + kk) * TD3 + 2*DD + h*HD + seg * 8);
        } else {
            *(uint4*)(Vhi + kk*72 + seg*8) = make_uint4(0u,0u,0u,0u);
        }
    }
    cp_commit();

    // ---- Q: fp16 load + fp32 rope -> fp16, row-major [q][d] ----
#pragma unroll
    for (int it = 0; it < 2; it++) {
        int item = tid + it * 256;
        int row = item & 63, j4 = item >> 6;
        int t = q0 + row;
        const __half* src = qbase + (size_t)t * TD3 + h * HD;
        uint2 u0 = *(const uint2*)(src + j4 * 4);
        uint2 u1 = *(const uint2*)(src + j4 * 4 + 32);
        float2 f0 = __half22float2(*(__half2*)&u0.x);
        float2 f1 = __half22float2(*(__half2*)&u0.y);
        float2 f2 = __half22float2(*(__half2*)&u1.x);
        float2 f3 = __half22float2(*(__half2*)&u1.y);
        const float4* tb = (const float4*)(tab + (size_t)t * 64 + j4 * 8);
        float4 t0 = tb[0], t1 = tb[1];
        float o[8];
        o[0]=f0.x*t0.x - f2.x*t0.y;  o[1]=f0.x*t0.y + f2.x*t0.x;
        o[2]=f0.y*t0.z - f2.y*t0.w;  o[3]=f0.y*t0.w + f2.y*t0.z;
        o[4]=f1.x*t1.x - f3.x*t1.y;  o[5]=f1.x*t1.y + f3.x*t1.x;
        o[6]=f1.y*t1.z - f3.y*t1.w;  o[7]=f1.y*t1.w + f3.y*t1.z;
        uint4 ph = make_uint4(
            packh2(__float2half_rn(o[0]),__float2half_rn(o[1])),
            packh2(__float2half_rn(o[2]),__float2half_rn(o[3])),
            packh2(__float2half_rn(o[4]),__float2half_rn(o[5])),
            packh2(__float2half_rn(o[6]),__float2half_rn(o[7])));
        *(uint4*)(Qh + row * 72 + j4 * 8) = ph;
    }
    // ---- K: fp16 load + fp32 rope -> fp16 row-major [token][d] ----
#pragma unroll
    for (int it = 0; it < 6; it++) {
        int item = tid + it * 256;
        int kk = item % 192, j4 = item / 192;
        if (kk < klen) {
            int t = ks + kk;
            const __half* src = qbase + (size_t)t * TD3 + DD + h * HD;
            uint2 u0 = *(const uint2*)(src + j4 * 4);
            uint2 u1 = *(const uint2*)(src + j4 * 4 + 32);
            float2 f0 = __half22float2(*(__half2*)&u0.x);
            float2 f1 = __half22float2(*(__half2*)&u0.y);
            float2 f2 = __half22float2(*(__half2*)&u1.x);
            float2 f3 = __half22float2(*(__half2*)&u1.y);
            const float4* tb = (const float4*)(tab + (size_t)t * 64 + j4 * 8);
            float4 t0 = tb[0], t1 = tb[1];
            float o[8];
            o[0]=f0.x*t0.x - f2.x*t0.y;  o[1]=f0.x*t0.y + f2.x*t0.x;
            o[2]=f0.y*t0.z - f2.y*t0.w;  o[3]=f0.y*t0.w + f2.y*t0.z;
            o[4]=f1.x*t1.x - f3.x*t1.y;  o[5]=f1.x*t1.y + f3.x*t1.x;
            o[6]=f1.y*t1.z - f3.y*t1.w;  o[7]=f1.y*t1.w + f3.y*t1.z;
            uint4 ph = make_uint4(
                packh2(__float2half_rn(o[0]),__float2half_rn(o[1])),
                packh2(__float2half_rn(o[2]),__float2half_rn(o[3])),
                packh2(__float2half_rn(o[4]),__float2half_rn(o[5])),
                packh2(__float2half_rn(o[6]),__float2half_rn(o[7])));
            *(uint4*)(Kh + kk * 72 + j4 * 8) = ph;
        }
    }
    if (tid < 192) Ms[tid] = (tid < klen) ? amask[b*TT + ks + tid] : 0;
    cp_wait<0>();
    __syncthreads();

    // ---- QK^T on HMMA: warp tile 32(q) x 48(k), K-dim 64 ----
    const int lane = tid & 31;
    const int warp = tid >> 5;
    const int wm = warp & 1;       // q half
    const int wn = warp >> 1;      // k quarter (48 cols)
    const int g = lane >> 2, t = lane & 3;
    const uint32_t qh_base = smem_u32(Qh);
    const uint32_t kh_base = smem_u32(Kh);

    float c[2][6][4];
#pragma unroll
    for (int mi = 0; mi < 2; mi++)
#pragma unroll
        for (int ni = 0; ni < 6; ni++)
#pragma unroll
            for (int r = 0; r < 4; r++) c[mi][ni][r] = 0.f;

    const uint32_t a_row = (uint32_t)(wm * 32 + (lane & 15));
    const uint32_t a_colb = (uint32_t)((lane >> 4) * 16);
    const uint32_t b_row4 = (uint32_t)(wn * 48 + (lane & 7) + ((lane >> 4) << 3));
    const uint32_t b_colb4 = (uint32_t)(((lane >> 3) & 1) * 16);

#pragma unroll
    for (int kstep = 0; kstep < 4; kstep++) {
        uint32_t a[2][4];
#pragma unroll
        for (int mi = 0; mi < 2; mi++)
            ldsm_x4(a[mi][0], a[mi][1], a[mi][2], a[mi][3],
                    qh_base + (a_row + mi * 16) * 144 + kstep * 32 + a_colb);
        uint32_t bf[6][2];
#pragma unroll
        for (int p = 0; p < 3; p++)
            ldsm_x4(bf[2*p][0], bf[2*p][1], bf[2*p+1][0], bf[2*p+1][1],
                    kh_base + (b_row4 + p * 16) * 144 + kstep * 32 + b_colb4);
#pragma unroll
        for (int mi = 0; mi < 2; mi++)
#pragma unroll
            for (int ni = 0; ni < 6; ni++)
                mma16816(c[mi][ni], a[mi], bf[ni]);
    }

    // ---- mask + row max ----
    const float scale = 0.125f;
    float mx[2][2] = { {-1e30f,-1e30f}, {-1e30f,-1e30f} };
#pragma unroll
    for (int mi = 0; mi < 2; mi++)
#pragma unroll
        for (int hh = 0; hh < 2; hh++) {
            int qg = q0 + wm*32 + mi*16 + g + hh*8;
#pragma unroll
            for (int ni = 0; ni < 6; ni++)
#pragma unroll
                for (int cc = 0; cc < 2; cc++) {
                    int kk = wn*48 + ni*8 + 2*t + cc;
                    int kg = ks + kk;
                    bool ok = (Ms[kk] != 0) && (abs(qg - kg) <= WIN);
                    float v = ok ? c[mi][ni][hh*2+cc] * scale : -1e30f;
                    c[mi][ni][hh*2+cc] = v;
                    mx[mi][hh] = fmaxf(mx[mi][hh], v);
                }
        }
#pragma unroll
    for (int mi = 0; mi < 2; mi++)
#pragma unroll
        for (int hh = 0; hh < 2; hh++) {
            float m = mx[mi][hh];
            m = fmaxf(m, __shfl_xor_sync(0xffffffffu, m, 1));
            m = fmaxf(m, __shfl_xor_sync(0xffffffffu, m, 2));
            mx[mi][hh] = m;
        }
    if (t == 0) {
#pragma unroll
        for (int mi = 0; mi < 2; mi++)
#pragma unroll
            for (int hh = 0; hh < 2; hh++)
                pmax[wn*64 + wm*32 + mi*16 + g + hh*8] = mx[mi][hh];
    }
    // Barrier publishes pmax AND retires all Qh/Kh reads -> Ph may overwrite.
    __syncthreads();

    // ---- exp + row sum, write Ph (fp16, aliases Qh+Kh) ----
    float sum[2][2] = { {0.f,0.f}, {0.f,0.f} };
#pragma unroll
    for (int mi = 0; mi < 2; mi++)
#pragma unroll
        for (int hh = 0; hh < 2; hh++) {
            int row = wm*32 + mi*16 + g + hh*8;
            float gm = fmaxf(fmaxf(pmax[row], pmax[64+row]),
                             fmaxf(pmax[128+row], pmax[192+row]));
#pragma unroll
            for (int ni = 0; ni < 6; ni++) {
                float e0 = __expf(c[mi][ni][hh*2+0] - gm);
                float e1 = __expf(c[mi][ni][hh*2+1] - gm);
                sum[mi][hh] += e0 + e1;
                *(uint32_t*)(Ph + row*200 + wn*48 + ni*8 + 2*t) =
                    packh2(__float2half_rn(e0), __float2half_rn(e1));
            }
        }
#pragma unroll
    for (int mi = 0; mi < 2; mi++)
#pragma unroll
        for (int hh = 0; hh < 2; hh++) {
            float s = sum[mi][hh];
            s += __shfl_xor_sync(0xffffffffu, s, 1);
            s += __shfl_xor_sync(0xffffffffu, s, 2);
            sum[mi][hh] = s;
        }
    if (t == 0) {
#pragma unroll
        for (int mi = 0; mi < 2; mi++)
#pragma unroll
            for (int hh = 0; hh < 2; hh++)
                psum[wn*64 + wm*32 + mi*16 + g + hh*8] = sum[mi][hh];
    }
    __syncthreads();

    // ---- PV on HMMA: warp tile 32(q) x 16(d), K-dim 192 ----
    const int wm2 = warp & 1;      // q half
    const int wn2 = warp >> 1;     // d quarter (16 cols)
    const uint32_t ph_base  = smem_u32(Ph);

    float o[2][2][4];
#pragma unroll
    for (int mi = 0; mi < 2; mi++)
#pragma unroll
        for (int ni = 0; ni < 2; ni++)
#pragma unroll
            for (int r = 0; r < 4; r++) o[mi][ni][r] = 0.f;

    const uint32_t pa_row  = (uint32_t)(wm2 * 32 + (lane & 15));
    const uint32_t pa_colb = (uint32_t)((lane >> 4) * 16);
    const uint32_t v_row  = (uint32_t)(lane & 15);
    const uint32_t v_colb = (uint32_t)(((lane >> 4) << 3) * 2);

#pragma unroll
    for (int ks2 = 0; ks2 < 12; ks2++) {
        uint32_t a[2][4];
#pragma unroll
        for (int mi = 0; mi < 2; mi++)
            ldsm_x4(a[mi][0], a[mi][1], a[mi][2], a[mi][3],
                    ph_base + (pa_row + mi * 16) * 400 + ks2 * 32 + pa_colb);
        uint32_t bh[2][2];
        ldsm_x4t(bh[0][0], bh[0][1], bh[1][0], bh[1][1],
                 vhi_smem + (ks2 * 16 + v_row) * 144 + (wn2 * 16) * 2 + v_colb);
#pragma unroll
        for (int mi = 0; mi < 2; mi++)
#pragma unroll
            for (int ni = 0; ni < 2; ni++)
                mma16816(o[mi][ni], a[mi], bh[ni]);
    }

    // ---- epilogue: normalize + write fp16 operand for Wo GEMM ----
#pragma unroll
    for (int mi = 0; mi < 2; mi++)
#pragma unroll
        for (int hh = 0; hh < 2; hh++) {
            int qq = wm2*32 + mi*16 + g + hh*8;
            float tot = psum[qq] + psum[64+qq] + psum[128+qq] + psum[192+qq];
            float r = 1.f / fmaxf(tot, 1e-30f);
#pragma unroll
            for (int ni = 0; ni < 2; ni++) {
                int d = wn2*16 + ni*8 + 2*t;
                uint32_t pair = packh2(__float2half_rn(o[mi][ni][hh*2+0] * r),
                                       __float2half_rn(o[mi][ni][hh*2+1] * r));
                *(uint32_t*)(attnx + (size_t)(b*TT + q0 + qq) * KK + h*HD + d) = pair;
            }
        }
}

// ---------------------------------------------------------------------------
extern "C" void kernel_launch(void* const* d_in, const int* in_sizes, int n_in,
                              void* d_out, int out_size)
{
    const float* hs   = (const float*)d_in[0];
    const int*   am   = (const int*)d_in[1];
    const float* Wqkv = (const float*)d_in[2];
    const float* Wo   = (const float*)d_in[3];
    float* out = (float*)d_out;

    void* p;
    cudaGetSymbolAddress(&p, g_qkvh);  __half* qkvh  = (__half*)p;
    cudaGetSymbolAddress(&p, g_ah);    __half* ah    = (__half*)p;
    cudaGetSymbolAddress(&p, g_attnx); __half* attnx = (__half*)p;
    cudaGetSymbolAddress(&p, g_wqkvh); __half* wqkvh = (__half*)p;
    cudaGetSymbolAddress(&p, g_woh);   __half* woh   = (__half*)p;
    cudaGetSymbolAddress(&p, g_tab);   float*  tab   = (float*)p;

    cudaFuncSetAttribute(attn_kernel,
                         cudaFuncAttributeMaxDynamicSharedMemorySize,
                         ATTN_SMEM_BYTES);
    cudaFuncSetAttribute(gemm_mma<true>,
                         cudaFuncAttributeMaxDynamicSharedMemorySize,
                         GEMM_SMEM);
    cudaFuncSetAttribute(gemm_mma<false>,
                         cudaFuncAttributeMaxDynamicSharedMemorySize,
                         GEMM_SMEM);

    const int M = BB * TT;                 // 8192

    // 1) fp32 -> fp16 (weights + hidden) + rope table, single launch
    conv_all<<<((TD3*DD + DD*DD + M*DD)/4 + TT*32 + 255)/256, 256>>>(
        Wqkv, Wo, hs, wqkvh, woh, ah, tab);

    // 2) QKV projection (fp16 output)
    gemm_mma<true><<<dim3(TD3/128, M/128), 256, GEMM_SMEM>>>(ah, wqkvh, qkvh, TD3);

    // 3) attention (2 CTAs/SM; x4 ldsm forms)
    dim3 ga(TT/64, NH, BB);
    attn_kernel<<<ga, 256, ATTN_SMEM_BYTES>>>(qkvh, am, tab, attnx);

    // 4) output projection (fp32 output)
    gemm_mma<false><<<dim3(DD/128, M/128), 256, GEMM_SMEM>>>(attnx, woh, out, DD);
}

// round 17
// speedup vs baseline: 1.2395x; 1.2395x over previous
#include <cuda_runtime.h>
#include <cuda_fp16.h>
#include <math.h>
#include <stdint.h>

#define BB 4
#define TT 2048
#define DD 768
#define NH 12
#define HD 64
#define WIN 64
#define TD3 (3*DD)
#define KK 768             // GEMM K (plain fp16 both operands)
#define KC 64              // k per pipeline chunk
#define NC (KK/KC)         // 12 chunks
#define PS 3               // pipeline stages
#define LDT 72             // padded smem row (fp16 elems) -> 144 bytes
#define TILE_BYTES (128*LDT*2)          // 18432 per operand tile
#define STAGE_BYTES (2*TILE_BYTES)      // 36864
#define GEMM_SMEM (PS*STAGE_BYTES)      // 110592

// attention smem layout (bytes).  Ph ALIASES the union of Qh and Kh.
#define QH_OFF   0                       // Qh fp16 [64][72]   9216B
#define KH_OFF   9216                    // Kh fp16 [192][72] 27648B (ends 36864)
#define PH_OFF   0                       // Ph fp16 [64][200] 25600B (alias Qh+Kh)
#define VHI_OFF  36864                   // Vhi fp16 [192][72] 27648B
#define PMAX_OFF 64512                   // fp32 [4][64] 1024B
#define PSUM_OFF 65536                   // fp32 [4][64] 1024B
#define MS_OFF   66560                   // int [192] 768B
#define ATTN_SMEM_BYTES 67328

// ---------------- scratch (device globals: allocation-free rule) -----------
__device__ __half g_qkvh[(size_t)BB*TT*TD3];         // [B,T,3D] fp16 (q,k ROPED)
__device__ __half g_ah  [(size_t)BB*TT*KK];          // hidden fp16
__device__ __half g_attnx[(size_t)BB*TT*KK];         // attn out fp16
__device__ __half g_wqkvh[(size_t)TD3*KK];           // Wqkv fp16 (rows PERMUTED)
__device__ __half g_woh [(size_t)DD*KK];             // Wo fp16
__device__ float  g_tab [(size_t)TT*64];             // rope (cos,sin) pairs [t][j]

typedef unsigned long long u64;

// ---------------- PTX helpers (baseline ISA only) ---------------------------
__device__ __forceinline__ uint32_t smem_u32(const void* p){
    uint32_t a;
    asm("{ .reg .u64 t; cvta.to.shared.u64 t, %1; cvt.u32.u64 %0, t; }"
        : "=r"(a) : "l"(p));
    return a;
}
__device__ __forceinline__ void cp16(uint32_t d, const void* s){
    asm volatile("cp.async.cg.shared.global [%0], [%1], 16;"
                 :: "r"(d), "l"(s) : "memory");
}
__device__ __forceinline__ void cp_commit(){
    asm volatile("cp.async.commit_group;" ::: "memory");
}
template<int N>
__device__ __forceinline__ void cp_wait(){
    asm volatile("cp.async.wait_group %0;" :: "n"(N) : "memory");
}
__device__ __forceinline__ void ldsm_x4(uint32_t &r0,uint32_t &r1,uint32_t &r2,uint32_t &r3,
                                        uint32_t addr){
    asm volatile("ldmatrix.sync.aligned.m8n8.x4.shared.b16 {%0,%1,%2,%3}, [%4];"
                 : "=r"(r0),"=r"(r1),"=r"(r2),"=r"(r3) : "r"(addr));
}
__device__ __forceinline__ void ldsm_x4t(uint32_t &r0,uint32_t &r1,uint32_t &r2,uint32_t &r3,
                                         uint32_t addr){
    asm volatile("ldmatrix.sync.aligned.m8n8.x4.trans.shared.b16 {%0,%1,%2,%3}, [%4];"
                 : "=r"(r0),"=r"(r1),"=r"(r2),"=r"(r3) : "r"(addr));
}
__device__ __forceinline__ void mma16816(float* d, const uint32_t* a, const uint32_t* b){
    asm volatile("mma.sync.aligned.m16n8k16.row.col.f32.f16.f16.f32 "
        "{%0,%1,%2,%3}, {%4,%5,%6,%7}, {%8,%9}, {%0,%1,%2,%3};"
        : "+f"(d[0]),"+f"(d[1]),"+f"(d[2]),"+f"(d[3])
        : "r"(a[0]),"r"(a[1]),"r"(a[2]),"r"(a[3]), "r"(b[0]),"r"(b[1]));
}
__device__ __forceinline__ uint32_t packh2(__half a, __half b){
    return (uint32_t)__half_as_ushort(a) | ((uint32_t)__half_as_ushort(b) << 16);
}

// ---------------------------------------------------------------------------
// fp32 -> fp16 conversion (weights + hidden) + rope table, one launch.
// Wqkv rows [0,1536) are PERMUTED so the QKV GEMM emits rope pairs adjacently:
//   within head: f<32 -> row base+2f,  f>=32 -> row base+2(f-32)+1.
// ---------------------------------------------------------------------------
__global__ void conv_all(const float* __restrict__ wqkv, const float* __restrict__ wo,
                         const float* __restrict__ hs,
                         __half* __restrict__ wqkvh, __half* __restrict__ woh,
                         __half* __restrict__ ah, float* __restrict__ tab)
{
    const int n1 = TD3*DD/4;
    const int n2 = DD*DD/4;
    const int n3 = BB*TT*DD/4;
    const int n4 = TT*32;                 // rope table entries
    int idx = blockIdx.x * blockDim.x + threadIdx.x;
    if (idx >= n1 + n2 + n3 + n4) return;
    if (idx >= n1 + n2 + n3) {
        int i = idx - n1 - n2 - n3;
        int t = i >> 5, j = i & 31;
        const float c0 = 0.41524101186092029f;   // log2(10000)/32
        float inv = exp2f(-c0 * (float)j);
        float sn, cs;
        sincosf((float)t * inv, &sn, &cs);
        tab[t*64 + 2*j]     = cs;
        tab[t*64 + 2*j + 1] = sn;
        return;
    }
    const float* src; __half* dst; int i;
    bool permute = false;
    if (idx < n1)            { src = wqkv; dst = wqkvh; i = idx; permute = true; }
    else if (idx < n1 + n2)  { src = wo;   dst = woh;   i = idx - n1; }
    else                     { src = hs;   dst = ah;    i = idx - n1 - n2; }
    float4 v = *(const float4*)(src + (size_t)i*4);
    uint2 o = make_uint2(packh2(__float2half_rn(v.x), __float2half_rn(v.y)),
                         packh2(__float2half_rn(v.z), __float2half_rn(v.w)));
    int row = i / 192, col4 = i - row * 192;
    if (permute && row < 1536) {
        int base = row & ~63, f = row & 63;
        row = (f < 32) ? (base + 2*f) : (base + 2*(f - 32) + 1);
    }
    *(uint2*)(dst + (size_t)row * KK + col4 * 4) = o;
}

// ---------------------------------------------------------------------------
// HMMA GEMM: C[m,n] = sum_{k<768} A[m,k] * B[n,k]   (fp16 -> fp32 or fp16)
// HOUT=true additionally applies RoPE to output cols < 1536 (qkv layout),
// using the row-permuted B so each acc pair = (x[j], x[j+32]).
// ---------------------------------------------------------------------------
template<bool HOUT>
__global__ void __launch_bounds__(256, 2)
gemm_mma(const __half* __restrict__ A, const __half* __restrict__ B,
         void* __restrict__ Cv, int N, const float* __restrict__ tab)
{
    extern __shared__ __align__(16) char smem[];
    const uint32_t sb = smem_u32(smem);
    const int tid  = threadIdx.x;
    const int lane = tid & 31;
    const int warp = tid >> 5;
    const int bm = blockIdx.y * 128;
    const int bn = blockIdx.x * 128;
    const int wm = warp & 1;
    const int wn = warp >> 1;

    const __half* asp[4]; uint32_t adf[4];
    const __half* bsp[4]; uint32_t bdf[4];
#pragma unroll
    for (int h = 0; h < 4; h++) {
        int idx = tid + h * 256;
        int row = idx >> 3, seg = idx & 7;
        asp[h] = A + (size_t)(bm + row) * KK + seg * 8;
        bsp[h] = B + (size_t)(bn + row) * KK + seg * 8;
        adf[h] = (uint32_t)(row * (LDT*2) + seg * 16);
        bdf[h] = adf[h] + TILE_BYTES;
    }

#pragma unroll
    for (int s = 0; s < PS - 1; s++) {
        uint32_t st = sb + s * STAGE_BYTES;
#pragma unroll
        for (int h = 0; h < 4; h++) {
            cp16(st + adf[h], asp[h] + s * KC);
            cp16(st + bdf[h], bsp[h] + s * KC);
        }
        cp_commit();
    }

    float acc[4][4][4];
#pragma unroll
    for (int mi = 0; mi < 4; mi++)
#pragma unroll
        for (int ni = 0; ni < 4; ni++)
#pragma unroll
            for (int r = 0; r < 4; r++) acc[mi][ni][r] = 0.f;

    const uint32_t a_row = (uint32_t)(wm * 64 + (lane & 15));
    const uint32_t a_colb = (uint32_t)((lane >> 4) * 16);
    const uint32_t b_row4 = (uint32_t)(wn * 32 + (lane & 7) + ((lane >> 4) << 3));
    const uint32_t b_colb4 = (uint32_t)(((lane >> 3) & 1) * 16);

    for (int i = 0; i < NC; i++) {
        cp_wait<PS - 2>();
        __syncthreads();

        int nc = i + PS - 1;
        if (nc < NC) {
            uint32_t st = sb + (nc % PS) * STAGE_BYTES;
#pragma unroll
            for (int h = 0; h < 4; h++) {
                cp16(st + adf[h], asp[h] + nc * KC);
                cp16(st + bdf[h], bsp[h] + nc * KC);
            }
        }
        cp_commit();

        uint32_t st = sb + (i % PS) * STAGE_BYTES;
#pragma unroll
        for (int ks = 0; ks < 4; ks++) {
            uint32_t a[4][4], b[4][2];
#pragma unroll
            for (int mi = 0; mi < 4; mi++) {
                uint32_t addr = st + (a_row + mi * 16) * (LDT*2) + ks * 32 + a_colb;
                ldsm_x4(a[mi][0], a[mi][1], a[mi][2], a[mi][3], addr);
            }
#pragma unroll
            for (int p = 0; p < 2; p++) {
                uint32_t addr = st + TILE_BYTES + (b_row4 + p * 16) * (LDT*2)
                              + ks * 32 + b_colb4;
                ldsm_x4(b[2*p][0], b[2*p][1], b[2*p+1][0], b[2*p+1][1], addr);
            }
#pragma unroll
            for (int mi = 0; mi < 4; mi++)
#pragma unroll
                for (int ni = 0; ni < 4; ni++)
                    mma16816(acc[mi][ni], a[mi], b[ni]);
        }
    }

    const int g = lane >> 2, t = lane & 3;
    const bool rope = HOUT && (bn < 1536);   // uniform per CTA
#pragma unroll
    for (int mi = 0; mi < 4; mi++) {
        int m0 = bm + wm * 64 + mi * 16 + g;
#pragma unroll
        for (int ni = 0; ni < 4; ni++) {
            int n0 = bn + wn * 32 + ni * 8 + 2 * t;
            float v0 = acc[mi][ni][0], v1 = acc[mi][ni][1];
            float v2 = acc[mi][ni][2], v3 = acc[mi][ni][3];
            if (HOUT) {
                if (rope) {
                    int j2 = n0 & 63;
                    int t0 = m0 & (TT - 1), t1 = (m0 + 8) & (TT - 1);
                    float2 cs0 = *(const float2*)&tab[(size_t)t0 * 64 + j2];
                    float2 cs1 = *(const float2*)&tab[(size_t)t1 * 64 + j2];
                    float r0 = v0 * cs0.x - v1 * cs0.y;
                    float r1 = v0 * cs0.y + v1 * cs0.x;
                    float r2 = v2 * cs1.x - v3 * cs1.y;
                    float r3 = v2 * cs1.y + v3 * cs1.x;
                    v0 = r0; v1 = r1; v2 = r2; v3 = r3;
                }
                __half* C = (__half*)Cv;
                *(uint32_t*)&C[(size_t)m0 * N + n0] =
                    packh2(__float2half_rn(v0), __float2half_rn(v1));
                *(uint32_t*)&C[(size_t)(m0 + 8) * N + n0] =
                    packh2(__float2half_rn(v2), __float2half_rn(v3));
            } else {
                float* C = (float*)Cv;
                *(float2*)&C[(size_t)m0 * N + n0] = make_float2(v0, v1);
                *(float2*)&C[(size_t)(m0 + 8) * N + n0] = make_float2(v2, v3);
            }
        }
    }
}

// ---------------------------------------------------------------------------
// Sliding-window attention: q/k already ROPED in g_qkvh, so Q/K/V are all
// pure cp.async copies.  HMMA scores + softmax-on-fragments + HMMA PV.
// 2 CTAs/SM (Ph aliases Qh+Kh).
// ---------------------------------------------------------------------------
__global__ void __launch_bounds__(256, 2)
attn_kernel(const __half* __restrict__ qkvh, const int* __restrict__ amask,
            __half* __restrict__ attnx)
{
    extern __shared__ __align__(16) char sm[];
    __half* Qh   = (__half*)(sm + QH_OFF);    // [64][72]   (aliased by Ph)
    __half* Kh   = (__half*)(sm + KH_OFF);    // [192][72]  (aliased by Ph)
    __half* Ph   = (__half*)(sm + PH_OFF);    // [64][200]
    __half* Vhi  = (__half*)(sm + VHI_OFF);   // [192][72]
    float*  pmax = (float*)(sm + PMAX_OFF);   // [4][64]
    float*  psum = (float*)(sm + PSUM_OFF);   // [4][64]
    int*    Ms   = (int*)(sm + MS_OFF);       // [192]

    const int tid = threadIdx.x;
    const int qb = blockIdx.x, h = blockIdx.y, b = blockIdx.z;
    const int q0 = qb * 64;
    const int ks = max(0, q0 - WIN);
    const int ke = min(TT, q0 + 64 + WIN);
    const int klen = ke - ks;
    const __half* qbase = qkvh + (size_t)b * TT * TD3;
    const uint32_t qh_smem  = smem_u32(Qh);
    const uint32_t kh_smem  = smem_u32(Kh);
    const uint32_t vhi_smem = smem_u32(Vhi);

    // ---- Q: cp.async copy (roped fp16), 64 rows x 8 segs ----
#pragma unroll
    for (int it = 0; it < 2; it++) {
        int idx = tid + it * 256;
        int row = idx >> 3, seg = idx & 7;
        cp16(qh_smem + row * 144 + seg * 16,
             qbase + (size_t)(q0 + row) * TD3 + h*HD + seg * 8);
    }
    // ---- K: cp.async copy (roped fp16), zero-fill beyond klen ----
#pragma unroll
    for (int it = 0; it < 6; it++) {
        int idx = tid + it * 256;
        int kk = idx >> 3, seg = idx & 7;
        if (kk < klen) {
            cp16(kh_smem + kk * 144 + seg * 16,
                 qbase + (size_t)(ks + kk) * TD3 + DD + h*HD + seg * 8);
        } else {
            *(uint4*)(Kh + kk*72 + seg*8) = make_uint4(0u,0u,0u,0u);
        }
    }
    // ---- V: cp.async copy, zero-fill beyond klen ----
#pragma unroll
    for (int it = 0; it < 6; it++) {
        int idx = tid + it * 256;
        int kk = idx >> 3, seg = idx & 7;
        if (kk < klen) {
            cp16(vhi_smem + kk * 144 + seg * 16,
                 qbase + (size_t)(ks + kk) * TD3 + 2*DD + h*HD + seg * 8);
        } else {
            *(uint4*)(Vhi + kk*72 + seg*8) = make_uint4(0u,0u,0u,0u);
        }
    }
    cp_commit();
    if (tid < 192) Ms[tid] = (tid < klen) ? amask[b*TT + ks + tid] : 0;
    cp_wait<0>();
    __syncthreads();

    // ---- QK^T on HMMA: warp tile 32(q) x 48(k), K-dim 64 ----
    const int lane = tid & 31;
    const int warp = tid >> 5;
    const int wm = warp & 1;       // q half
    const int wn = warp >> 1;      // k quarter (48 cols)
    const int g = lane >> 2, t = lane & 3;

    float c[2][6][4];
#pragma unroll
    for (int mi = 0; mi < 2; mi++)
#pragma unroll
        for (int ni = 0; ni < 6; ni++)
#pragma unroll
            for (int r = 0; r < 4; r++) c[mi][ni][r] = 0.f;

    const uint32_t a_row = (uint32_t)(wm * 32 + (lane & 15));
    const uint32_t a_colb = (uint32_t)((lane >> 4) * 16);
    const uint32_t b_row4 = (uint32_t)(wn * 48 + (lane & 7) + ((lane >> 4) << 3));
    const uint32_t b_colb4 = (uint32_t)(((lane >> 3) & 1) * 16);

#pragma unroll
    for (int kstep = 0; kstep < 4; kstep++) {
        uint32_t a[2][4];
#pragma unroll
        for (int mi = 0; mi < 2; mi++)
            ldsm_x4(a[mi][0], a[mi][1], a[mi][2], a[mi][3],
                    qh_smem + (a_row + mi * 16) * 144 + kstep * 32 + a_colb);
        uint32_t bf[6][2];
#pragma unroll
        for (int p = 0; p < 3; p++)
            ldsm_x4(bf[2*p][0], bf[2*p][1], bf[2*p+1][0], bf[2*p+1][1],
                    kh_smem + (b_row4 + p * 16) * 144 + kstep * 32 + b_colb4);
#pragma unroll
        for (int mi = 0; mi < 2; mi++)
#pragma unroll
            for (int ni = 0; ni < 6; ni++)
                mma16816(c[mi][ni], a[mi], bf[ni]);
    }

    // ---- mask + row max ----
    const float scale = 0.125f;
    float mx[2][2] = { {-1e30f,-1e30f}, {-1e30f,-1e30f} };
#pragma unroll
    for (int mi = 0; mi < 2; mi++)
#pragma unroll
        for (int hh = 0; hh < 2; hh++) {
            int qg = q0 + wm*32 + mi*16 + g + hh*8;
#pragma unroll
            for (int ni = 0; ni < 6; ni++)
#pragma unroll
                for (int cc = 0; cc < 2; cc++) {
                    int kk = wn*48 + ni*8 + 2*t + cc;
                    int kg = ks + kk;
                    bool ok = (Ms[kk] != 0) && (abs(qg - kg) <= WIN);
                    float v = ok ? c[mi][ni][hh*2+cc] * scale : -1e30f;
                    c[mi][ni][hh*2+cc] = v;
                    mx[mi][hh] = fmaxf(mx[mi][hh], v);
                }
        }
#pragma unroll
    for (int mi = 0; mi < 2; mi++)
#pragma unroll
        for (int hh = 0; hh < 2; hh++) {
            float m = mx[mi][hh];
            m = fmaxf(m, __shfl_xor_sync(0xffffffffu, m, 1));
            m = fmaxf(m, __shfl_xor_sync(0xffffffffu, m, 2));
            mx[mi][hh] = m;
        }
    if (t == 0) {
#pragma unroll
        for (int mi = 0; mi < 2; mi++)
#pragma unroll
            for (int hh = 0; hh < 2; hh++)
                pmax[wn*64 + wm*32 + mi*16 + g + hh*8] = mx[mi][hh];
    }
    // Barrier publishes pmax AND retires all Qh/Kh reads -> Ph may overwrite.
    __syncthreads();

    // ---- exp + row sum, write Ph (fp16, aliases Qh+Kh) ----
    float sum[2][2] = { {0.f,0.f}, {0.f,0.f} };
#pragma unroll
    for (int mi = 0; mi < 2; mi++)
#pragma unroll
        for (int hh = 0; hh < 2; hh++) {
            int row = wm*32 + mi*16 + g + hh*8;
            float gm = fmaxf(fmaxf(pmax[row], pmax[64+row]),
                             fmaxf(pmax[128+row], pmax[192+row]));
#pragma unroll
            for (int ni = 0; ni < 6; ni++) {
                float e0 = __expf(c[mi][ni][hh*2+0] - gm);
                float e1 = __expf(c[mi][ni][hh*2+1] - gm);
                sum[mi][hh] += e0 + e1;
                *(uint32_t*)(Ph + row*200 + wn*48 + ni*8 + 2*t) =
                    packh2(__float2half_rn(e0), __float2half_rn(e1));
            }
        }
#pragma unroll
    for (int mi = 0; mi < 2; mi++)
#pragma unroll
        for (int hh = 0; hh < 2; hh++) {
            float s = sum[mi][hh];
            s += __shfl_xor_sync(0xffffffffu, s, 1);
            s += __shfl_xor_sync(0xffffffffu, s, 2);
            sum[mi][hh] = s;
        }
    if (t == 0) {
#pragma unroll
        for (int mi = 0; mi < 2; mi++)
#pragma unroll
            for (int hh = 0; hh < 2; hh++)
                psum[wn*64 + wm*32 + mi*16 + g + hh*8] = sum[mi][hh];
    }
    __syncthreads();

    // ---- PV on HMMA: warp tile 32(q) x 16(d), K-dim 192 ----
    const int wm2 = warp & 1;      // q half
    const int wn2 = warp >> 1;     // d quarter (16 cols)
    const uint32_t ph_base  = smem_u32(Ph);

    float o[2][2][4];
#pragma unroll
    for (int mi = 0; mi < 2; mi++)
#pragma unroll
        for (int ni = 0; ni < 2; ni++)
#pragma unroll
            for (int r = 0; r < 4; r++) o[mi][ni][r] = 0.f;

    const uint32_t pa_row  = (uint32_t)(wm2 * 32 + (lane & 15));
    const uint32_t pa_colb = (uint32_t)((lane >> 4) * 16);
    const uint32_t v_row  = (uint32_t)(lane & 15);
    const uint32_t v_colb = (uint32_t)(((lane >> 4) << 3) * 2);

#pragma unroll
    for (int ks2 = 0; ks2 < 12; ks2++) {
        uint32_t a[2][4];
#pragma unroll
        for (int mi = 0; mi < 2; mi++)
            ldsm_x4(a[mi][0], a[mi][1], a[mi][2], a[mi][3],
                    ph_base + (pa_row + mi * 16) * 400 + ks2 * 32 + pa_colb);
        uint32_t bh[2][2];
        ldsm_x4t(bh[0][0], bh[0][1], bh[1][0], bh[1][1],
                 vhi_smem + (ks2 * 16 + v_row) * 144 + (wn2 * 16) * 2 + v_colb);
#pragma unroll
        for (int mi = 0; mi < 2; mi++)
#pragma unroll
            for (int ni = 0; ni < 2; ni++)
                mma16816(o[mi][ni], a[mi], bh[ni]);
    }

    // ---- epilogue: normalize + write fp16 operand for Wo GEMM ----
#pragma unroll
    for (int mi = 0; mi < 2; mi++)
#pragma unroll
        for (int hh = 0; hh < 2; hh++) {
            int qq = wm2*32 + mi*16 + g + hh*8;
            float tot = psum[qq] + psum[64+qq] + psum[128+qq] + psum[192+qq];
            float r = 1.f / fmaxf(tot, 1e-30f);
#pragma unroll
            for (int ni = 0; ni < 2; ni++) {
                int d = wn2*16 + ni*8 + 2*t;
                uint32_t pair = packh2(__float2half_rn(o[mi][ni][hh*2+0] * r),
                                       __float2half_rn(o[mi][ni][hh*2+1] * r));
                *(uint32_t*)(attnx + (size_t)(b*TT + q0 + qq) * KK + h*HD + d) = pair;
            }
        }
}

// ---------------------------------------------------------------------------
extern "C" void kernel_launch(void* const* d_in, const int* in_sizes, int n_in,
                              void* d_out, int out_size)
{
    const float* hs   = (const float*)d_in[0];
    const int*   am   = (const int*)d_in[1];
    const float* Wqkv = (const float*)d_in[2];
    const float* Wo   = (const float*)d_in[3];
    float* out = (float*)d_out;

    void* p;
    cudaGetSymbolAddress(&p, g_qkvh);  __half* qkvh  = (__half*)p;
    cudaGetSymbolAddress(&p, g_ah);    __half* ah    = (__half*)p;
    cudaGetSymbolAddress(&p, g_attnx); __half* attnx = (__half*)p;
    cudaGetSymbolAddress(&p, g_wqkvh); __half* wqkvh = (__half*)p;
    cudaGetSymbolAddress(&p, g_woh);   __half* woh   = (__half*)p;
    cudaGetSymbolAddress(&p, g_tab);   float*  tab   = (float*)p;

    cudaFuncSetAttribute(attn_kernel,
                         cudaFuncAttributeMaxDynamicSharedMemorySize,
                         ATTN_SMEM_BYTES);
    cudaFuncSetAttribute(gemm_mma<true>,
                         cudaFuncAttributeMaxDynamicSharedMemorySize,
                         GEMM_SMEM);
    cudaFuncSetAttribute(gemm_mma<false>,
                         cudaFuncAttributeMaxDynamicSharedMemorySize,
                         GEMM_SMEM);

    const int M = BB * TT;                 // 8192

    // 1) fp32 -> fp16 (weights permuted + hidden) + rope table, one launch
    conv_all<<<((TD3*DD + DD*DD + M*DD)/4 + TT*32 + 255)/256, 256>>>(
        Wqkv, Wo, hs, wqkvh, woh, ah, tab);

    // 2) QKV projection with fused RoPE epilogue (fp16 output)
    gemm_mma<true><<<dim3(TD3/128, M/128), 256, GEMM_SMEM>>>(
        ah, wqkvh, qkvh, TD3, tab);

    // 3) attention (all-cp.async loads; HMMA scores + PV)
    dim3 ga(TT/64, NH, BB);
    attn_kernel<<<ga, 256, ATTN_SMEM_BYTES>>>(qkvh, am, attnx);

    // 4) output projection (fp32 output)
    gemm_mma<false><<<dim3(DD/128, M/128), 256, GEMM_SMEM>>>(
        attnx, woh, out, DD, tab);
}